// round 8
// baseline (speedup 1.0000x reference)
#include <cuda_runtime.h>
#include <cuda_bf16.h>
#include <stdint.h>
#include <math.h>

// Problem: gramBatch [B=8, C=8, N=1024, 16,16] fp32 -> out [8,1024,1024] fp32.
// out[b,i,j] = mean_c (sq_i + sq_j - 2*dot_c(i,j)) * rn_i * rn_j,
//   sq = sum_d g^2, rn = 1/sqrt(sum_d g^4).
// GEMM: pre-scale rows by rn (bf16); accumulate all c and K in fp32 registers
// via mma.sync m16n8k16 bf16. Rank-16 additive term stays fp32 in epilogue.
// R6->R7: 128-thread CTA, 4 warps of 64x64, fragment double-buffering.

#define BB 8
#define CC 8
#define NN 1024
#define DD 256

// bf16 pre-scaled rows, row-major [65536][256]
__device__ __align__(16) unsigned char g_bfb[(size_t)BB * CC * NN * DD * 2];
__device__ float g_u[BB * CC * NN]; // sq * rn
__device__ float g_r[BB * CC * NN]; // rn

// ---------------------------------------------------------------------------
// Prep: per-row reductions + bf16 pre-scaled rows (row-major).
// ---------------------------------------------------------------------------
__global__ void prep_kernel(const float* __restrict__ g) {
    int row = blockIdx.x * 8 + threadIdx.y;
    int lane = threadIdx.x;
    const float* p = g + (size_t)row * DD + lane * 8;
    float4 v0 = *(const float4*)(p);
    float4 v1 = *(const float4*)(p + 4);
    float vals[8] = {v0.x, v0.y, v0.z, v0.w, v1.x, v1.y, v1.z, v1.w};
    float s2 = 0.f, s4 = 0.f;
#pragma unroll
    for (int i = 0; i < 8; ++i) { float q = vals[i] * vals[i]; s2 += q; s4 += q * q; }
#pragma unroll
    for (int o = 16; o > 0; o >>= 1) {
        s2 += __shfl_xor_sync(0xFFFFFFFFu, s2, o);
        s4 += __shfl_xor_sync(0xFFFFFFFFu, s4, o);
    }
    float rn = 1.0f / sqrtf(s4);
    if (lane == 0) { g_u[row] = s2 * rn; g_r[row] = rn; }

    uint32_t w[4];
#pragma unroll
    for (int q = 0; q < 4; ++q) {
        __nv_bfloat162 h = __floats2bfloat162_rn(vals[2 * q] * rn, vals[2 * q + 1] * rn);
        w[q] = *(uint32_t*)&h;
    }
    *(uint4*)(g_bfb + (size_t)row * 512 + lane * 16) = make_uint4(w[0], w[1], w[2], w[3]);
}

// ---------------------------------------------------------------------------
// Helpers
// ---------------------------------------------------------------------------
__device__ __forceinline__ void ldsm_x4(uint32_t* r, uint32_t a) {
    asm volatile("ldmatrix.sync.aligned.m8n8.x4.shared.b16 {%0,%1,%2,%3}, [%4];"
        : "=r"(r[0]), "=r"(r[1]), "=r"(r[2]), "=r"(r[3]) : "r"(a));
}
__device__ __forceinline__ void mma16816(float* d, const uint32_t* a, uint32_t b0, uint32_t b1) {
    asm volatile("mma.sync.aligned.m16n8k16.row.col.f32.bf16.bf16.f32 "
        "{%0,%1,%2,%3}, {%4,%5,%6,%7}, {%8,%9}, {%0,%1,%2,%3};"
        : "+f"(d[0]), "+f"(d[1]), "+f"(d[2]), "+f"(d[3])
        : "r"(a[0]), "r"(a[1]), "r"(a[2]), "r"(a[3]), "r"(b0), "r"(b1));
}
#define CP_ASYNC(dst, src) \
    asm volatile("cp.async.cg.shared.global [%0], [%1], 16;" :: "r"(dst), "l"(src))
#define CP_COMMIT() asm volatile("cp.async.commit_group;")
#define CP_WAIT1() asm volatile("cp.async.wait_group 1;")
#define CP_WAIT0() asm volatile("cp.async.wait_group 0;")

// ---------------------------------------------------------------------------
// Main: per (tile-pair, b) CTA; 4 warps (2x2), warp tile 64x64.
// 32 chunks (8c x 4 k-chunks of 64), 3-stage cp.async ring,
// fragment double-buffering across ks.
// ---------------------------------------------------------------------------
__global__ __launch_bounds__(128, 2)
void gram_mma_kernel(float* __restrict__ out) {
    extern __shared__ unsigned char S[];
    uint32_t sbase;
    asm("{ .reg .u64 t; cvta.to.shared.u64 t, %1; cvt.u32.u64 %0, t; }"
        : "=r"(sbase) : "l"(S));

    float2* pA = (float2*)S;                 // [8][128] (u_a, r_a)
    float2* qB = (float2*)(S + 8192);        // [8][128] (r_b, u_b)
    const uint32_t TILES = sbase + 16384;    // 3 stages x (A 16KB + B 16KB)
    float* outT = (float*)(S + 16384);       // reused after GEMM: [128][130]

    int tid = threadIdx.x, lane = tid & 31, wid = tid >> 5;
    int warp_m = wid >> 1, warp_n = wid & 1;
    int pair = blockIdx.x, b = blockIdx.y;
    int it = 0, rem = pair;
    while (rem >= 8 - it) { rem -= 8 - it; ++it; }
    int jt = it + rem;

    // Epilogue scalars into smem.
    for (int idx = tid; idx < 1024; idx += 128) {
        int c = idx >> 7, i = idx & 127;
        int ra = (b * CC + c) * NN + it * 128 + i;
        int rb = (b * CC + c) * NN + jt * 128 + i;
        pA[idx] = make_float2(g_u[ra], g_r[ra]);
        qB[idx] = make_float2(g_r[rb], g_u[rb]);
    }

    // Per-lane cp.async slots: 8 float4 slots for A, same for B.
    // tile = 128 rows x 128 bytes (64 bf16 cols); 1024 slots of 16B.
    int ldr[8], ldq[8];
#pragma unroll
    for (int p = 0; p < 8; ++p) { int id = tid + p * 128; ldr[p] = id >> 3; ldq[p] = id & 7; }

    const size_t rowA0 = (size_t)(b * CC) * NN + it * 128;
    const size_t rowB0 = (size_t)(b * CC) * NN + jt * 128;

    // chunk ch: c = ch>>2, kt = (ch&3)*64; stage slot passed explicitly.
    auto issue = [&](int ch, int slot) {
        int c = ch >> 2, kt2 = (ch & 3) * 128; // kt*2 bytes
        uint32_t sA = TILES + (uint32_t)slot * 32768u;
        uint32_t sB = sA + 16384u;
        const unsigned char* gA = g_bfb + (rowA0 + (size_t)c * NN) * 512 + kt2;
        const unsigned char* gB = g_bfb + (rowB0 + (size_t)c * NN) * 512 + kt2;
#pragma unroll
        for (int p = 0; p < 8; ++p) {
            int r = ldr[p], q = ldq[p];
            uint32_t swz = (uint32_t)(r * 128 + ((q * 16) ^ ((r & 7) * 16)));
            CP_ASYNC(sA + swz, gA + (size_t)r * 512 + q * 16);
            CP_ASYNC(sB + swz, gB + (size_t)r * 512 + q * 16);
        }
        CP_COMMIT();
    };

    // Fragment addressing (per-lane constants). Rows are 128B; swizzle xor
    // depends only on (lane & 7).
    int arow = warp_m * 64 + (lane & 15);
    uint32_t aBase = (uint32_t)(arow * 128);
    uint32_t aXor = (uint32_t)((lane & 7) * 16);
    uint32_t aKadd = (uint32_t)((lane >> 4) * 16);
    int brow = warp_n * 64 + (lane & 7) + ((lane >> 4) << 3);
    uint32_t bBase = (uint32_t)(brow * 128);
    uint32_t bXor = (uint32_t)((lane & 7) * 16);
    uint32_t bKadd = (lane & 8) ? 16u : 0u;

    float acc[4][8][4];
#pragma unroll
    for (int mt = 0; mt < 4; ++mt)
#pragma unroll
        for (int nt = 0; nt < 8; ++nt)
#pragma unroll
            for (int e = 0; e < 4; ++e) acc[mt][nt][e] = 0.f;

    uint32_t afr[2][4][4], bfr[2][4][4];

    // Prologue: fill stages 0 and 1.
    issue(0, 0);
    issue(1, 1);

    int slot = 0;           // compute slot = ch % 3
    int fill = 2;           // next slot to fill = (ch+2) % 3
    for (int ch = 0; ch < 32; ++ch) {
        if (ch == 31) { CP_WAIT0(); } else { CP_WAIT1(); }
        __syncthreads();
        // Refill the slot freed at iter ch-1 (barrier above makes this safe).
        if (ch + 2 < 32) issue(ch + 2, fill);

        uint32_t sA = TILES + (uint32_t)slot * 32768u;
        uint32_t sB = sA + 16384u;

        // Load ks=0 fragments into buffer 0.
#pragma unroll
        for (int mt = 0; mt < 4; ++mt)
            ldsm_x4(afr[0][mt], sA + aBase + (uint32_t)(mt * 2048) + (aKadd ^ aXor));
#pragma unroll
        for (int g = 0; g < 4; ++g)
            ldsm_x4(bfr[0][g], sB + bBase + (uint32_t)(g * 2048) + (bKadd ^ bXor));

#pragma unroll
        for (int ks = 0; ks < 4; ++ks) {
            int cur = ks & 1, nxt = cur ^ 1;
            if (ks < 3) {
                uint32_t kb = (uint32_t)((ks + 1) * 32);
#pragma unroll
                for (int mt = 0; mt < 4; ++mt)
                    ldsm_x4(afr[nxt][mt],
                            sA + aBase + (uint32_t)(mt * 2048) + ((kb + aKadd) ^ aXor));
#pragma unroll
                for (int g = 0; g < 4; ++g)
                    ldsm_x4(bfr[nxt][g],
                            sB + bBase + (uint32_t)(g * 2048) + ((kb + bKadd) ^ bXor));
            }
#pragma unroll
            for (int mt = 0; mt < 4; ++mt)
#pragma unroll
                for (int nt = 0; nt < 8; ++nt)
                    mma16816(acc[mt][nt], afr[cur][mt],
                             bfr[cur][nt >> 1][(nt & 1) * 2],
                             bfr[cur][nt >> 1][(nt & 1) * 2 + 1]);
        }
        slot = (slot == 2) ? 0 : slot + 1;
        fill = (fill == 2) ? 0 : fill + 1;
    }
    __syncthreads();   // all MMAs done before outT overwrites the tile region

    // Stage dot sums into smem (stride 130 floats; float2-aligned).
#pragma unroll
    for (int mt = 0; mt < 4; ++mt) {
        int r1 = warp_m * 64 + mt * 16 + (lane >> 2);
#pragma unroll
        for (int nt = 0; nt < 8; ++nt) {
            int cb = warp_n * 64 + nt * 8 + (lane & 3) * 2;
            *(float2*)&outT[r1 * 130 + cb] = make_float2(acc[mt][nt][0], acc[mt][nt][1]);
            *(float2*)&outT[(r1 + 8) * 130 + cb] = make_float2(acc[mt][nt][2], acc[mt][nt][3]);
        }
    }
    __syncthreads();

    // Correction + direct store. Column jc constant per thread -> hoist qB regs.
    int jc = tid;  // 0..127
    unsigned long long qreg[8];
#pragma unroll
    for (int c = 0; c < 8; ++c)
        qreg[c] = *(unsigned long long*)&qB[c * 128 + jc];

    size_t ob = (size_t)b << 20;
    for (int idx = tid; idx < 16384; idx += 128) {
        int r = idx >> 7;
        float dot = outT[r * 130 + jc];
        unsigned long long t = 0ull;
#pragma unroll
        for (int c = 0; c < 8; ++c) {
            unsigned long long pa = *(unsigned long long*)&pA[c * 128 + r];
            asm("fma.rn.f32x2 %0, %1, %2, %0;" : "+l"(t) : "l"(pa), "l"(qreg[c]));
        }
        float2 tf = *(float2*)&t;
        float v = (tf.x + tf.y - 2.0f * dot) * 0.125f;
        out[ob + ((size_t)(it * 128 + r) << 10) + jt * 128 + jc] = v;
        outT[r * 130 + jc] = v;
    }

    if (it != jt) {
        __syncthreads();
        for (int idx = tid; idx < 16384; idx += 128) {
            int rr = idx >> 7, ic = idx & 127;
            out[ob + ((size_t)(jt * 128 + rr) << 10) + it * 128 + ic] = outT[ic * 130 + rr];
        }
    }
}

// ---------------------------------------------------------------------------
extern "C" void kernel_launch(void* const* d_in, const int* in_sizes, int n_in,
                              void* d_out, int out_size) {
    const float* g = (const float*)d_in[0];
    float* out = (float*)d_out;
    (void)in_sizes; (void)n_in; (void)out_size;

    cudaFuncSetAttribute(gram_mma_kernel,
                         cudaFuncAttributeMaxDynamicSharedMemorySize, 114688);

    prep_kernel<<<(BB * CC * NN) / 8, dim3(32, 8)>>>(g);
    gram_mma_kernel<<<dim3(36, BB), 128, 114688>>>(out);
}

// round 10
// speedup vs baseline: 1.0879x; 1.0879x over previous
#include <cuda_runtime.h>
#include <cuda_bf16.h>
#include <stdint.h>
#include <math.h>

// Problem: gramBatch [B=8, C=8, N=1024, 16,16] fp32 -> out [8,1024,1024] fp32.
// out[b,i,j] = mean_c (sq_i + sq_j - 2*dot_c(i,j)) * rn_i * rn_j,
//   sq = sum_d g^2, rn = 1/sqrt(sum_d g^4).
// GEMM: pre-scale rows by rn (bf16); accumulate all c and K in fp32 registers
// via mma.sync m16n8k16 bf16. Rank-16 additive term stays fp32 in epilogue.
// R8->R9: FIX block addressing (blk base was missing *4 on b and tile terms).
// Barrier-free mainloop: thread 0 feeds 3-slot ring with cp.async.bulk +
// mbarrier full/empty; consumer warps decoupled (no per-chunk __syncthreads).

#define BB 8
#define CC 8
#define NN 1024
#define DD 256

// Blocked bf16: block index (bc*8 + tile)*4 + kq, each 16KB (128 rows x 128B, swizzled).
__device__ __align__(1024) unsigned char g_bfb[(size_t)BB * CC * 8 * 4 * 16384];
__device__ float g_u[BB * CC * NN]; // sq * rn
__device__ float g_r[BB * CC * NN]; // rn

// ---------------------------------------------------------------------------
// Prep: per-row reductions + bf16 pre-scaled rows in blocked swizzled layout.
// ---------------------------------------------------------------------------
__global__ void prep_kernel(const float* __restrict__ g) {
    int row = blockIdx.x * 8 + threadIdx.y;       // 0..65535
    int lane = threadIdx.x;
    const float* p = g + (size_t)row * DD + lane * 8;
    float4 v0 = *(const float4*)(p);
    float4 v1 = *(const float4*)(p + 4);
    float vals[8] = {v0.x, v0.y, v0.z, v0.w, v1.x, v1.y, v1.z, v1.w};
    float s2 = 0.f, s4 = 0.f;
#pragma unroll
    for (int i = 0; i < 8; ++i) { float q = vals[i] * vals[i]; s2 += q; s4 += q * q; }
#pragma unroll
    for (int o = 16; o > 0; o >>= 1) {
        s2 += __shfl_xor_sync(0xFFFFFFFFu, s2, o);
        s4 += __shfl_xor_sync(0xFFFFFFFFu, s4, o);
    }
    float rn = 1.0f / sqrtf(s4);
    if (lane == 0) { g_u[row] = s2 * rn; g_r[row] = rn; }

    uint32_t w[4];
#pragma unroll
    for (int q = 0; q < 4; ++q) {
        __nv_bfloat162 h = __floats2bfloat162_rn(vals[2 * q] * rn, vals[2 * q + 1] * rn);
        w[q] = *(uint32_t*)&h;
    }
    int bc = row >> 10, n = row & (NN - 1);
    int tile = n >> 7, r = n & 127;
    int kq = lane >> 3, q = lane & 7;             // k-quarter (64 elems = 128B)
    uint32_t off = (uint32_t)(r * 128 + ((q * 16) ^ ((r & 7) * 16)));
    *(uint4*)(g_bfb + (((size_t)(bc * 8 + tile) * 4 + kq) << 14) + off) =
        make_uint4(w[0], w[1], w[2], w[3]);
}

// ---------------------------------------------------------------------------
// Helpers
// ---------------------------------------------------------------------------
__device__ __forceinline__ void ldsm_x4(uint32_t* r, uint32_t a) {
    asm volatile("ldmatrix.sync.aligned.m8n8.x4.shared.b16 {%0,%1,%2,%3}, [%4];"
        : "=r"(r[0]), "=r"(r[1]), "=r"(r[2]), "=r"(r[3]) : "r"(a));
}
__device__ __forceinline__ void mma16816(float* d, const uint32_t* a, uint32_t b0, uint32_t b1) {
    asm volatile("mma.sync.aligned.m16n8k16.row.col.f32.bf16.bf16.f32 "
        "{%0,%1,%2,%3}, {%4,%5,%6,%7}, {%8,%9}, {%0,%1,%2,%3};"
        : "+f"(d[0]), "+f"(d[1]), "+f"(d[2]), "+f"(d[3])
        : "r"(a[0]), "r"(a[1]), "r"(a[2]), "r"(a[3]), "r"(b0), "r"(b1));
}
#define MBAR_INIT(a, n) \
    asm volatile("mbarrier.init.shared.b64 [%0], %1;" :: "r"(a), "r"(n) : "memory")
#define MBAR_EXPECT_TX(a, n) \
    asm volatile("mbarrier.arrive.expect_tx.shared.b64 _, [%0], %1;" :: "r"(a), "r"(n) : "memory")
#define MBAR_ARRIVE(a) \
    asm volatile("mbarrier.arrive.shared.b64 _, [%0];" :: "r"(a) : "memory")
#define MBAR_WAIT(a, ph) do { \
    uint32_t _m = (a); uint32_t _p = (ph); uint32_t _done; \
    asm volatile("{\n\t.reg .pred p;\n\t" \
        "mbarrier.try_wait.parity.acquire.cta.shared::cta.b64 p, [%1], %2;\n\t" \
        "selp.b32 %0, 1, 0, p;\n\t}" : "=r"(_done) : "r"(_m), "r"(_p) : "memory"); \
    if (!_done) { \
        asm volatile("{\n\t.reg .pred P1;\n\t" \
            "WL_%=:\n\t" \
            "mbarrier.try_wait.parity.acquire.cta.shared::cta.b64 P1, [%0], %1, 0x989680;\n\t" \
            "@P1 bra.uni WD_%=;\n\t" \
            "bra.uni WL_%=;\n\t" \
            "WD_%=:\n\t}" :: "r"(_m), "r"(_p) : "memory"); \
    } \
} while (0)
#define BULK_CP(dst, src, nbytes, mb) \
    asm volatile("cp.async.bulk.shared::cta.global.mbarrier::complete_tx::bytes [%0], [%1], %2, [%3];" \
        :: "r"(dst), "l"(src), "r"(nbytes), "r"(mb) : "memory")

// ---------------------------------------------------------------------------
// Main: per (tile-pair, b) CTA; 8 warps (2x4), warp tile 64x32.
// 32 chunks (8c x 4 k-quarters of 64), 3-slot mbarrier ring fed by thread 0
// with cp.async.bulk; consumer warps fully decoupled (no block barrier).
// ---------------------------------------------------------------------------
__global__ __launch_bounds__(256, 2)
void gram_mma_kernel(float* __restrict__ out) {
    extern __shared__ unsigned char S[];
    uint32_t sbase;
    asm("{ .reg .u64 t; cvta.to.shared.u64 t, %1; cvt.u32.u64 %0, t; }"
        : "=r"(sbase) : "l"(S));

    float2* pA = (float2*)S;                   // [8][128] (u_a, r_a)  8KB
    float2* qB = (float2*)(S + 8192);          // [8][128] (r_b, u_b)  8KB
    const uint32_t TILES = sbase + 16384;      // 3 slots x (A 16KB + B 16KB)
    float* outT = (float*)(S + 16384);         // reused after GEMM: [128][130]
    const uint32_t MB = sbase + 16384 + 98304; // 6 mbarriers (48B)
    // full[s] = MB + s*8 ; empty[s] = MB + 24 + s*8

    int tid = threadIdx.x, lane = tid & 31, wid = tid >> 5;
    int warp_m = wid >> 2, warp_n = wid & 3;
    int pair = blockIdx.x, b = blockIdx.y;
    int it = 0, rem = pair;
    while (rem >= 8 - it) { rem -= 8 - it; ++it; }
    int jt = it + rem;

    if (tid == 0) {
#pragma unroll
        for (int s = 0; s < 3; ++s) { MBAR_INIT(MB + s * 8, 1u); MBAR_INIT(MB + 24 + s * 8, 8u); }
    }

    // Epilogue scalars into smem.
    for (int idx = tid; idx < 1024; idx += 256) {
        int c = idx >> 7, i = idx & 127;
        int ra = (b * CC + c) * NN + it * 128 + i;
        int rb = (b * CC + c) * NN + jt * 128 + i;
        pA[idx] = make_float2(g_u[ra], g_r[ra]);
        qB[idx] = make_float2(g_r[rb], g_u[rb]);
    }
    __syncthreads();   // mbarrier init + scalars visible

    // Block index = b*256 + c*32 + tile*4 + kq  (x16KB each).
    const size_t blkA0 = (size_t)(b * 256 + it * 4) << 14;
    const size_t blkB0 = (size_t)(b * 256 + jt * 4) << 14;

    // chunk ch: c = ch>>2, kq = ch&3.
    auto produce = [&](int ch, int slot) {
        int c = ch >> 2, kq = ch & 3;
        size_t boff = ((size_t)(c * 32 + kq)) << 14;
        uint32_t mb = MB + (uint32_t)slot * 8;
        uint32_t dA = TILES + (uint32_t)slot * 32768u;
        MBAR_EXPECT_TX(mb, 32768u);
        BULK_CP(dA, (const void*)(g_bfb + blkA0 + boff), 16384u, mb);
        BULK_CP(dA + 16384u, (const void*)(g_bfb + blkB0 + boff), 16384u, mb);
    };

    if (tid == 0) { produce(0, 0); produce(1, 1); produce(2, 2); }

    // Fragment addressing (per-lane constants). Rows are 128B (k64).
    int arow = warp_m * 64 + (lane & 15);
    uint32_t aBase = (uint32_t)(arow * 128);
    uint32_t aXor = (uint32_t)((lane & 7) * 16);
    uint32_t aKadd = (uint32_t)((lane >> 4) * 16);
    int brow = warp_n * 32 + (lane & 7) + ((lane >> 4) << 3);
    uint32_t bBase = (uint32_t)(brow * 128);
    uint32_t bXor = (uint32_t)((lane & 7) * 16);
    uint32_t bKadd = (lane & 8) ? 16u : 0u;

    float acc[4][4][4];
#pragma unroll
    for (int mt = 0; mt < 4; ++mt)
#pragma unroll
        for (int nt = 0; nt < 4; ++nt)
#pragma unroll
            for (int e = 0; e < 4; ++e) acc[mt][nt][e] = 0.f;

    for (int ch = 0; ch < 32; ++ch) {
        int slot = ch % 3;
        // Producer: refill two chunks ahead (slot freed after chunk ch-1).
        if (tid == 0 && ch >= 1 && ch + 2 < 32) {
            int n2 = ch + 2, s2 = n2 % 3;
            MBAR_WAIT(MB + 24 + (uint32_t)s2 * 8, (uint32_t)(((n2 - 3) / 3) & 1));
            produce(n2, s2);
        }
        // Consumer: wait chunk data.
        MBAR_WAIT(MB + (uint32_t)slot * 8, (uint32_t)((ch / 3) & 1));

        uint32_t sA = TILES + (uint32_t)slot * 32768u;
        uint32_t sB = sA + 16384u;
#pragma unroll
        for (int ks = 0; ks < 4; ++ks) {
            uint32_t kb = (uint32_t)(ks * 32);
            uint32_t afr[4][4], bfr[2][4];
#pragma unroll
            for (int mt = 0; mt < 4; ++mt)
                ldsm_x4(afr[mt], sA + aBase + (uint32_t)(mt * 2048) + ((kb + aKadd) ^ aXor));
#pragma unroll
            for (int g2 = 0; g2 < 2; ++g2)
                ldsm_x4(bfr[g2], sB + bBase + (uint32_t)(g2 * 2048) + ((kb + bKadd) ^ bXor));
#pragma unroll
            for (int mt = 0; mt < 4; ++mt)
#pragma unroll
                for (int nt = 0; nt < 4; ++nt)
                    mma16816(acc[mt][nt], afr[mt], bfr[nt >> 1][(nt & 1) * 2],
                             bfr[nt >> 1][(nt & 1) * 2 + 1]);
        }
        if (lane == 0) MBAR_ARRIVE(MB + 24 + (uint32_t)slot * 8);
    }
    __syncthreads();   // all MMAs done before outT overwrites the tile region

    // Stage dot sums into smem (stride 130 floats; float2-aligned).
#pragma unroll
    for (int mt = 0; mt < 4; ++mt) {
        int r1 = warp_m * 64 + mt * 16 + (lane >> 2);
#pragma unroll
        for (int nt = 0; nt < 4; ++nt) {
            int cb = warp_n * 32 + nt * 8 + (lane & 3) * 2;
            *(float2*)&outT[r1 * 130 + cb] = make_float2(acc[mt][nt][0], acc[mt][nt][1]);
            *(float2*)&outT[(r1 + 8) * 130 + cb] = make_float2(acc[mt][nt][2], acc[mt][nt][3]);
        }
    }
    __syncthreads();

    // Correction + direct store. Column jc constant per thread -> hoist qB regs.
    int jc = tid & 127;
    unsigned long long qreg[8];
#pragma unroll
    for (int c = 0; c < 8; ++c)
        qreg[c] = *(unsigned long long*)&qB[c * 128 + jc];

    size_t ob = (size_t)b << 20;
    for (int idx = tid; idx < 16384; idx += 256) {
        int r = idx >> 7;
        float dot = outT[r * 130 + jc];
        unsigned long long t = 0ull;
#pragma unroll
        for (int c = 0; c < 8; ++c) {
            unsigned long long pa = *(unsigned long long*)&pA[c * 128 + r];
            asm("fma.rn.f32x2 %0, %1, %2, %0;" : "+l"(t) : "l"(pa), "l"(qreg[c]));
        }
        float2 tf = *(float2*)&t;
        float v = (tf.x + tf.y - 2.0f * dot) * 0.125f;
        out[ob + ((size_t)(it * 128 + r) << 10) + jt * 128 + jc] = v;
        outT[r * 130 + jc] = v;
    }

    if (it != jt) {
        __syncthreads();
        for (int idx = tid; idx < 16384; idx += 256) {
            int rr = idx >> 7, ic = idx & 127;
            out[ob + ((size_t)(jt * 128 + rr) << 10) + it * 128 + ic] = outT[ic * 130 + rr];
        }
    }
}

// ---------------------------------------------------------------------------
extern "C" void kernel_launch(void* const* d_in, const int* in_sizes, int n_in,
                              void* d_out, int out_size) {
    const float* g = (const float*)d_in[0];
    float* out = (float*)d_out;
    (void)in_sizes; (void)n_in; (void)out_size;

    cudaFuncSetAttribute(gram_mma_kernel,
                         cudaFuncAttributeMaxDynamicSharedMemorySize, 114752);

    prep_kernel<<<(BB * CC * NN) / 8, dim3(32, 8)>>>(g);
    gram_mma_kernel<<<dim3(36, BB), 256, 114752>>>(out);
}